// round 2
// baseline (speedup 1.0000x reference)
#include <cuda_runtime.h>

// Problem constants
#define B_  1024
#define L_  2
#define D_  1024
#define F_  32768
#define K1  (L_*D_)        // encoder K = 2048
#define N2  (L_*D_)        // decoder N (flattened l*D+d) = 2048
#define SPLITK 4
#define KSPL (F_/SPLITK)   // 8192

// Scratch (no cudaMalloc allowed): f activations + decoder split-K partials
__device__ float g_f[1024ull * 32768ull];              // 128 MB
__device__ float g_part[(size_t)SPLITK * 1024ull * 2048ull]; // 32 MB

// ---------------------------------------------------------------------------
// 128x128x16 double-buffered SGEMM core. 256 threads, 8x8 per thread.
// A: row-major [.., lda] (M rows x K cols), B: row-major [K rows x .., ldb].
// All dims assumed divisible (M tile 128, N tile 128, K % 16 == 0).
// ---------------------------------------------------------------------------
__device__ __forceinline__ void gemm_tile(
    const float* __restrict__ A, int lda,
    const float* __restrict__ Bp, int ldb,
    int K, float acc[8][8],
    float (&As)[2][16][128], float (&Bs)[2][16][128])
{
    const int tid  = threadIdx.x;
    const int aRow = tid >> 2;          // 0..63 (second pass +64)
    const int aCol = (tid & 3) << 2;    // 0,4,8,12
    const int bRow = tid >> 5;          // 0..7  (second pass +8)
    const int bCol = (tid & 31) << 2;   // 0..124
    const int tx   = (tid & 15) << 3;   // col0 of 8x8 frag
    const int ty   = (tid >> 4) << 3;   // row0 of 8x8 frag

    float4 a0, a1, b0, b1;

    // Prefetch tile 0
    a0 = *reinterpret_cast<const float4*>(A + (size_t)aRow      * lda + aCol);
    a1 = *reinterpret_cast<const float4*>(A + (size_t)(aRow+64) * lda + aCol);
    b0 = *reinterpret_cast<const float4*>(Bp + (size_t)bRow     * ldb + bCol);
    b1 = *reinterpret_cast<const float4*>(Bp + (size_t)(bRow+8) * ldb + bCol);

    As[0][aCol+0][aRow]    = a0.x; As[0][aCol+1][aRow]    = a0.y;
    As[0][aCol+2][aRow]    = a0.z; As[0][aCol+3][aRow]    = a0.w;
    As[0][aCol+0][aRow+64] = a1.x; As[0][aCol+1][aRow+64] = a1.y;
    As[0][aCol+2][aRow+64] = a1.z; As[0][aCol+3][aRow+64] = a1.w;
    *reinterpret_cast<float4*>(&Bs[0][bRow  ][bCol]) = b0;
    *reinterpret_cast<float4*>(&Bs[0][bRow+8][bCol]) = b1;
    __syncthreads();

    const int T = K >> 4;
    for (int t = 0; t < T; t++) {
        const int cur = t & 1;

        if (t + 1 < T) {
            const float* An = A  + (size_t)(t+1)*16;        // advance along K (cols of A)
            const float* Bn = Bp + (size_t)(t+1)*16 * ldb;  // advance along K (rows of B)
            a0 = *reinterpret_cast<const float4*>(An + (size_t)aRow      * lda + aCol);
            a1 = *reinterpret_cast<const float4*>(An + (size_t)(aRow+64) * lda + aCol);
            b0 = *reinterpret_cast<const float4*>(Bn + (size_t)bRow      * ldb + bCol);
            b1 = *reinterpret_cast<const float4*>(Bn + (size_t)(bRow+8)  * ldb + bCol);
        }

        #pragma unroll
        for (int kk = 0; kk < 16; kk++) {
            float a[8], b[8];
            *reinterpret_cast<float4*>(a)   = *reinterpret_cast<const float4*>(&As[cur][kk][ty]);
            *reinterpret_cast<float4*>(a+4) = *reinterpret_cast<const float4*>(&As[cur][kk][ty+4]);
            *reinterpret_cast<float4*>(b)   = *reinterpret_cast<const float4*>(&Bs[cur][kk][tx]);
            *reinterpret_cast<float4*>(b+4) = *reinterpret_cast<const float4*>(&Bs[cur][kk][tx+4]);
            #pragma unroll
            for (int i = 0; i < 8; i++)
                #pragma unroll
                for (int j = 0; j < 8; j++)
                    acc[i][j] = fmaf(a[i], b[j], acc[i][j]);
        }

        if (t + 1 < T) {
            const int nxt = cur ^ 1;
            As[nxt][aCol+0][aRow]    = a0.x; As[nxt][aCol+1][aRow]    = a0.y;
            As[nxt][aCol+2][aRow]    = a0.z; As[nxt][aCol+3][aRow]    = a0.w;
            As[nxt][aCol+0][aRow+64] = a1.x; As[nxt][aCol+1][aRow+64] = a1.y;
            As[nxt][aCol+2][aRow+64] = a1.z; As[nxt][aCol+3][aRow+64] = a1.w;
            *reinterpret_cast<float4*>(&Bs[nxt][bRow  ][bCol]) = b0;
            *reinterpret_cast<float4*>(&Bs[nxt][bRow+8][bCol]) = b1;
            __syncthreads();
        }
    }
}

// ---------------------------------------------------------------------------
// Encoder: f = relu(X[1024,2048] @ W_enc[2048,32768] + b_enc)  -> g_f
// grid (8, 256), block 256
// ---------------------------------------------------------------------------
__global__ __launch_bounds__(256, 2)
void enc_kernel(const float* __restrict__ x,
                const float* __restrict__ W,
                const float* __restrict__ bias)
{
    __shared__ float As[2][16][128];
    __shared__ float Bs[2][16][128];
    float acc[8][8];
    #pragma unroll
    for (int i = 0; i < 8; i++)
        #pragma unroll
        for (int j = 0; j < 8; j++) acc[i][j] = 0.0f;

    const float* A  = x + (size_t)blockIdx.x * 128 * K1;
    const float* Bp = W + (size_t)blockIdx.y * 128;
    gemm_tile(A, K1, Bp, F_, K1, acc, As, Bs);

    const int tid = threadIdx.x;
    const int tx  = (tid & 15) << 3;
    const int ty  = (tid >> 4) << 3;
    const int row0 = blockIdx.x * 128 + ty;
    const int col0 = blockIdx.y * 128 + tx;

    float bi[8];
    *reinterpret_cast<float4*>(bi)   = *reinterpret_cast<const float4*>(&bias[col0]);
    *reinterpret_cast<float4*>(bi+4) = *reinterpret_cast<const float4*>(&bias[col0+4]);

    #pragma unroll
    for (int i = 0; i < 8; i++) {
        float4 v0, v1;
        v0.x = fmaxf(acc[i][0] + bi[0], 0.0f);
        v0.y = fmaxf(acc[i][1] + bi[1], 0.0f);
        v0.z = fmaxf(acc[i][2] + bi[2], 0.0f);
        v0.w = fmaxf(acc[i][3] + bi[3], 0.0f);
        v1.x = fmaxf(acc[i][4] + bi[4], 0.0f);
        v1.y = fmaxf(acc[i][5] + bi[5], 0.0f);
        v1.z = fmaxf(acc[i][6] + bi[6], 0.0f);
        v1.w = fmaxf(acc[i][7] + bi[7], 0.0f);
        float* dst = g_f + (size_t)(row0 + i) * F_ + col0;
        *reinterpret_cast<float4*>(dst)     = v0;
        *reinterpret_cast<float4*>(dst + 4) = v1;
    }
}

// ---------------------------------------------------------------------------
// Decoder split-K partials: part[kz] = f[:, kz*8192:(kz+1)*8192] @ Wd_l slice
// grid (8, 16, SPLITK), block 256.  Column j = l*D + d; a 128-wide tile stays
// within one l, so B is a plain row-major [F,1024] slab per l.
// ---------------------------------------------------------------------------
__global__ __launch_bounds__(256, 2)
void dec_kernel(const float* __restrict__ Wd)
{
    __shared__ float As[2][16][128];
    __shared__ float Bs[2][16][128];
    float acc[8][8];
    #pragma unroll
    for (int i = 0; i < 8; i++)
        #pragma unroll
        for (int j = 0; j < 8; j++) acc[i][j] = 0.0f;

    const int n0 = blockIdx.y * 128;
    const int l  = n0 / D_;
    const int d0 = n0 % D_;
    const int kz = blockIdx.z;

    const float* A  = g_f + (size_t)blockIdx.x * 128 * F_ + (size_t)kz * KSPL;
    const float* Bp = Wd + (size_t)l * F_ * D_ + (size_t)kz * KSPL * D_ + d0;
    gemm_tile(A, F_, Bp, D_, KSPL, acc, As, Bs);

    const int tid = threadIdx.x;
    const int tx  = (tid & 15) << 3;
    const int ty  = (tid >> 4) << 3;
    const int row0 = blockIdx.x * 128 + ty;
    const int col0 = n0 + tx;

    float* C = g_part + (size_t)kz * B_ * N2;
    #pragma unroll
    for (int i = 0; i < 8; i++) {
        float4 v0, v1;
        v0.x = acc[i][0]; v0.y = acc[i][1]; v0.z = acc[i][2]; v0.w = acc[i][3];
        v1.x = acc[i][4]; v1.y = acc[i][5]; v1.z = acc[i][6]; v1.w = acc[i][7];
        float* dst = C + (size_t)(row0 + i) * N2 + col0;
        *reinterpret_cast<float4*>(dst)     = v0;
        *reinterpret_cast<float4*>(dst + 4) = v1;
    }
}

// ---------------------------------------------------------------------------
// Reduce split-K partials + b_dec -> output [B, L*D]
// ---------------------------------------------------------------------------
__global__ void reduce_kernel(float* __restrict__ out,
                              const float* __restrict__ b_dec)
{
    const size_t i  = (size_t)blockIdx.x * blockDim.x + threadIdx.x; // float4 idx
    const size_t n4 = (size_t)B_ * N2 / 4;                           // 524288
    if (i >= n4) return;
    const float4* p = reinterpret_cast<const float4*>(g_part);
    float4 v0 = p[i];
    float4 v1 = p[i + n4];
    float4 v2 = p[i + 2*n4];
    float4 v3 = p[i + 3*n4];
    const int col = (int)((i * 4) & (N2 - 1));
    float4 bb = *reinterpret_cast<const float4*>(&b_dec[col]);
    float4 r;
    r.x = v0.x + v1.x + v2.x + v3.x + bb.x;
    r.y = v0.y + v1.y + v2.y + v3.y + bb.y;
    r.z = v0.z + v1.z + v2.z + v3.z + bb.z;
    r.w = v0.w + v1.w + v2.w + v3.w + bb.w;
    reinterpret_cast<float4*>(out)[i] = r;
}

// ---------------------------------------------------------------------------
extern "C" void kernel_launch(void* const* d_in, const int* in_sizes, int n_in,
                              void* d_out, int out_size)
{
    const float* x     = (const float*)d_in[0];
    const float* W_enc = (const float*)d_in[1];
    const float* b_enc = (const float*)d_in[2];
    const float* W_dec = (const float*)d_in[3];
    const float* b_dec = (const float*)d_in[4];
    float* out = (float*)d_out;

    dim3 ge(8, 256);
    enc_kernel<<<ge, 256>>>(x, W_enc, b_enc);

    dim3 gd(8, 16, SPLITK);
    dec_kernel<<<gd, 256>>>(W_dec);

    reduce_kernel<<<2048, 256>>>(out, b_dec);
}

// round 3
// speedup vs baseline: 1.0004x; 1.0004x over previous
#include <cuda_runtime.h>

// Problem constants
#define B_  1024
#define L_  2
#define D_  1024
#define F_  32768
#define K1  (L_*D_)        // encoder K = 2048
#define N2  (L_*D_)        // decoder N (flattened l*D+d) = 2048
#define SPLITK 4
#define KSPL (F_/SPLITK)   // 8192

// Scratch (no cudaMalloc allowed): f activations + decoder split-K partials
__device__ float g_f[1024ull * 32768ull];              // 128 MB
__device__ float g_part[(size_t)SPLITK * 1024ull * 2048ull]; // 32 MB

// ---------------------------------------------------------------------------
// 128x128x16 double-buffered SGEMM core. 256 threads, 8x8 per thread.
// A: row-major [.., lda] (M rows x K cols), B: row-major [K rows x .., ldb].
// All dims assumed divisible (M tile 128, N tile 128, K % 16 == 0).
// ---------------------------------------------------------------------------
__device__ __forceinline__ void gemm_tile(
    const float* __restrict__ A, int lda,
    const float* __restrict__ Bp, int ldb,
    int K, float acc[8][8],
    float (&As)[2][16][128], float (&Bs)[2][16][128])
{
    const int tid  = threadIdx.x;
    const int aRow = tid >> 2;          // 0..63 (second pass +64)
    const int aCol = (tid & 3) << 2;    // 0,4,8,12
    const int bRow = tid >> 5;          // 0..7  (second pass +8)
    const int bCol = (tid & 31) << 2;   // 0..124
    const int tx   = (tid & 15) << 3;   // col0 of 8x8 frag
    const int ty   = (tid >> 4) << 3;   // row0 of 8x8 frag

    float4 a0, a1, b0, b1;

    // Prefetch tile 0
    a0 = *reinterpret_cast<const float4*>(A + (size_t)aRow      * lda + aCol);
    a1 = *reinterpret_cast<const float4*>(A + (size_t)(aRow+64) * lda + aCol);
    b0 = *reinterpret_cast<const float4*>(Bp + (size_t)bRow     * ldb + bCol);
    b1 = *reinterpret_cast<const float4*>(Bp + (size_t)(bRow+8) * ldb + bCol);

    As[0][aCol+0][aRow]    = a0.x; As[0][aCol+1][aRow]    = a0.y;
    As[0][aCol+2][aRow]    = a0.z; As[0][aCol+3][aRow]    = a0.w;
    As[0][aCol+0][aRow+64] = a1.x; As[0][aCol+1][aRow+64] = a1.y;
    As[0][aCol+2][aRow+64] = a1.z; As[0][aCol+3][aRow+64] = a1.w;
    *reinterpret_cast<float4*>(&Bs[0][bRow  ][bCol]) = b0;
    *reinterpret_cast<float4*>(&Bs[0][bRow+8][bCol]) = b1;
    __syncthreads();

    const int T = K >> 4;
    for (int t = 0; t < T; t++) {
        const int cur = t & 1;

        if (t + 1 < T) {
            const float* An = A  + (size_t)(t+1)*16;        // advance along K (cols of A)
            const float* Bn = Bp + (size_t)(t+1)*16 * ldb;  // advance along K (rows of B)
            a0 = *reinterpret_cast<const float4*>(An + (size_t)aRow      * lda + aCol);
            a1 = *reinterpret_cast<const float4*>(An + (size_t)(aRow+64) * lda + aCol);
            b0 = *reinterpret_cast<const float4*>(Bn + (size_t)bRow      * ldb + bCol);
            b1 = *reinterpret_cast<const float4*>(Bn + (size_t)(bRow+8)  * ldb + bCol);
        }

        #pragma unroll
        for (int kk = 0; kk < 16; kk++) {
            float a[8], b[8];
            *reinterpret_cast<float4*>(a)   = *reinterpret_cast<const float4*>(&As[cur][kk][ty]);
            *reinterpret_cast<float4*>(a+4) = *reinterpret_cast<const float4*>(&As[cur][kk][ty+4]);
            *reinterpret_cast<float4*>(b)   = *reinterpret_cast<const float4*>(&Bs[cur][kk][tx]);
            *reinterpret_cast<float4*>(b+4) = *reinterpret_cast<const float4*>(&Bs[cur][kk][tx+4]);
            #pragma unroll
            for (int i = 0; i < 8; i++)
                #pragma unroll
                for (int j = 0; j < 8; j++)
                    acc[i][j] = fmaf(a[i], b[j], acc[i][j]);
        }

        if (t + 1 < T) {
            const int nxt = cur ^ 1;
            As[nxt][aCol+0][aRow]    = a0.x; As[nxt][aCol+1][aRow]    = a0.y;
            As[nxt][aCol+2][aRow]    = a0.z; As[nxt][aCol+3][aRow]    = a0.w;
            As[nxt][aCol+0][aRow+64] = a1.x; As[nxt][aCol+1][aRow+64] = a1.y;
            As[nxt][aCol+2][aRow+64] = a1.z; As[nxt][aCol+3][aRow+64] = a1.w;
            *reinterpret_cast<float4*>(&Bs[nxt][bRow  ][bCol]) = b0;
            *reinterpret_cast<float4*>(&Bs[nxt][bRow+8][bCol]) = b1;
            __syncthreads();
        }
    }
}

// ---------------------------------------------------------------------------
// Encoder: f = relu(X[1024,2048] @ W_enc[2048,32768] + b_enc)  -> g_f
// grid (8, 256), block 256
// ---------------------------------------------------------------------------
__global__ __launch_bounds__(256, 2)
void enc_kernel(const float* __restrict__ x,
                const float* __restrict__ W,
                const float* __restrict__ bias)
{
    __shared__ float As[2][16][128];
    __shared__ float Bs[2][16][128];
    float acc[8][8];
    #pragma unroll
    for (int i = 0; i < 8; i++)
        #pragma unroll
        for (int j = 0; j < 8; j++) acc[i][j] = 0.0f;

    const float* A  = x + (size_t)blockIdx.x * 128 * K1;
    const float* Bp = W + (size_t)blockIdx.y * 128;
    gemm_tile(A, K1, Bp, F_, K1, acc, As, Bs);

    const int tid = threadIdx.x;
    const int tx  = (tid & 15) << 3;
    const int ty  = (tid >> 4) << 3;
    const int row0 = blockIdx.x * 128 + ty;
    const int col0 = blockIdx.y * 128 + tx;

    float bi[8];
    *reinterpret_cast<float4*>(bi)   = *reinterpret_cast<const float4*>(&bias[col0]);
    *reinterpret_cast<float4*>(bi+4) = *reinterpret_cast<const float4*>(&bias[col0+4]);

    #pragma unroll
    for (int i = 0; i < 8; i++) {
        float4 v0, v1;
        v0.x = fmaxf(acc[i][0] + bi[0], 0.0f);
        v0.y = fmaxf(acc[i][1] + bi[1], 0.0f);
        v0.z = fmaxf(acc[i][2] + bi[2], 0.0f);
        v0.w = fmaxf(acc[i][3] + bi[3], 0.0f);
        v1.x = fmaxf(acc[i][4] + bi[4], 0.0f);
        v1.y = fmaxf(acc[i][5] + bi[5], 0.0f);
        v1.z = fmaxf(acc[i][6] + bi[6], 0.0f);
        v1.w = fmaxf(acc[i][7] + bi[7], 0.0f);
        float* dst = g_f + (size_t)(row0 + i) * F_ + col0;
        *reinterpret_cast<float4*>(dst)     = v0;
        *reinterpret_cast<float4*>(dst + 4) = v1;
    }
}

// ---------------------------------------------------------------------------
// Decoder split-K partials: part[kz] = f[:, kz*8192:(kz+1)*8192] @ Wd_l slice
// grid (8, 16, SPLITK), block 256.  Column j = l*D + d; a 128-wide tile stays
// within one l, so B is a plain row-major [F,1024] slab per l.
// ---------------------------------------------------------------------------
__global__ __launch_bounds__(256, 2)
void dec_kernel(const float* __restrict__ Wd)
{
    __shared__ float As[2][16][128];
    __shared__ float Bs[2][16][128];
    float acc[8][8];
    #pragma unroll
    for (int i = 0; i < 8; i++)
        #pragma unroll
        for (int j = 0; j < 8; j++) acc[i][j] = 0.0f;

    const int n0 = blockIdx.y * 128;
    const int l  = n0 / D_;
    const int d0 = n0 % D_;
    const int kz = blockIdx.z;

    const float* A  = g_f + (size_t)blockIdx.x * 128 * F_ + (size_t)kz * KSPL;
    const float* Bp = Wd + (size_t)l * F_ * D_ + (size_t)kz * KSPL * D_ + d0;
    gemm_tile(A, F_, Bp, D_, KSPL, acc, As, Bs);

    const int tid = threadIdx.x;
    const int tx  = (tid & 15) << 3;
    const int ty  = (tid >> 4) << 3;
    const int row0 = blockIdx.x * 128 + ty;
    const int col0 = n0 + tx;

    float* C = g_part + (size_t)kz * B_ * N2;
    #pragma unroll
    for (int i = 0; i < 8; i++) {
        float4 v0, v1;
        v0.x = acc[i][0]; v0.y = acc[i][1]; v0.z = acc[i][2]; v0.w = acc[i][3];
        v1.x = acc[i][4]; v1.y = acc[i][5]; v1.z = acc[i][6]; v1.w = acc[i][7];
        float* dst = C + (size_t)(row0 + i) * N2 + col0;
        *reinterpret_cast<float4*>(dst)     = v0;
        *reinterpret_cast<float4*>(dst + 4) = v1;
    }
}

// ---------------------------------------------------------------------------
// Reduce split-K partials + b_dec -> output [B, L*D]
// ---------------------------------------------------------------------------
__global__ void reduce_kernel(float* __restrict__ out,
                              const float* __restrict__ b_dec)
{
    const size_t i  = (size_t)blockIdx.x * blockDim.x + threadIdx.x; // float4 idx
    const size_t n4 = (size_t)B_ * N2 / 4;                           // 524288
    if (i >= n4) return;
    const float4* p = reinterpret_cast<const float4*>(g_part);
    float4 v0 = p[i];
    float4 v1 = p[i + n4];
    float4 v2 = p[i + 2*n4];
    float4 v3 = p[i + 3*n4];
    const int col = (int)((i * 4) & (N2 - 1));
    float4 bb = *reinterpret_cast<const float4*>(&b_dec[col]);
    float4 r;
    r.x = v0.x + v1.x + v2.x + v3.x + bb.x;
    r.y = v0.y + v1.y + v2.y + v3.y + bb.y;
    r.z = v0.z + v1.z + v2.z + v3.z + bb.z;
    r.w = v0.w + v1.w + v2.w + v3.w + bb.w;
    reinterpret_cast<float4*>(out)[i] = r;
}

// ---------------------------------------------------------------------------
extern "C" void kernel_launch(void* const* d_in, const int* in_sizes, int n_in,
                              void* d_out, int out_size)
{
    const float* x     = (const float*)d_in[0];
    const float* W_enc = (const float*)d_in[1];
    const float* b_enc = (const float*)d_in[2];
    const float* W_dec = (const float*)d_in[3];
    const float* b_dec = (const float*)d_in[4];
    float* out = (float*)d_out;

    dim3 ge(8, 256);
    enc_kernel<<<ge, 256>>>(x, W_enc, b_enc);

    dim3 gd(8, 16, SPLITK);
    dec_kernel<<<gd, 256>>>(W_dec);

    reduce_kernel<<<2048, 256>>>(out, b_dec);
}

// round 4
// speedup vs baseline: 1.0012x; 1.0009x over previous
#include <cuda_runtime.h>

// Problem constants
#define B_  1024
#define L_  2
#define D_  1024
#define F_  32768
#define K1  (L_*D_)        // encoder K = 2048
#define N2  (L_*D_)        // decoder N (flattened l*D+d) = 2048
#define SPLITK 4
#define KSPL (F_/SPLITK)   // 8192

// Scratch (no cudaMalloc allowed): f activations + decoder split-K partials
__device__ float g_f[1024ull * 32768ull];              // 128 MB
__device__ float g_part[(size_t)SPLITK * 1024ull * 2048ull]; // 32 MB

// ---------------------------------------------------------------------------
// 128x128x16 double-buffered SGEMM core. 256 threads, 8x8 per thread.
// A: row-major [.., lda] (M rows x K cols), B: row-major [K rows x .., ldb].
// All dims assumed divisible (M tile 128, N tile 128, K % 16 == 0).
// ---------------------------------------------------------------------------
__device__ __forceinline__ void gemm_tile(
    const float* __restrict__ A, int lda,
    const float* __restrict__ Bp, int ldb,
    int K, float acc[8][8],
    float (&As)[2][16][128], float (&Bs)[2][16][128])
{
    const int tid  = threadIdx.x;
    const int aRow = tid >> 2;          // 0..63 (second pass +64)
    const int aCol = (tid & 3) << 2;    // 0,4,8,12
    const int bRow = tid >> 5;          // 0..7  (second pass +8)
    const int bCol = (tid & 31) << 2;   // 0..124
    const int tx   = (tid & 15) << 3;   // col0 of 8x8 frag
    const int ty   = (tid >> 4) << 3;   // row0 of 8x8 frag

    float4 a0, a1, b0, b1;

    // Prefetch tile 0
    a0 = *reinterpret_cast<const float4*>(A + (size_t)aRow      * lda + aCol);
    a1 = *reinterpret_cast<const float4*>(A + (size_t)(aRow+64) * lda + aCol);
    b0 = *reinterpret_cast<const float4*>(Bp + (size_t)bRow     * ldb + bCol);
    b1 = *reinterpret_cast<const float4*>(Bp + (size_t)(bRow+8) * ldb + bCol);

    As[0][aCol+0][aRow]    = a0.x; As[0][aCol+1][aRow]    = a0.y;
    As[0][aCol+2][aRow]    = a0.z; As[0][aCol+3][aRow]    = a0.w;
    As[0][aCol+0][aRow+64] = a1.x; As[0][aCol+1][aRow+64] = a1.y;
    As[0][aCol+2][aRow+64] = a1.z; As[0][aCol+3][aRow+64] = a1.w;
    *reinterpret_cast<float4*>(&Bs[0][bRow  ][bCol]) = b0;
    *reinterpret_cast<float4*>(&Bs[0][bRow+8][bCol]) = b1;
    __syncthreads();

    const int T = K >> 4;
    for (int t = 0; t < T; t++) {
        const int cur = t & 1;

        if (t + 1 < T) {
            const float* An = A  + (size_t)(t+1)*16;        // advance along K (cols of A)
            const float* Bn = Bp + (size_t)(t+1)*16 * ldb;  // advance along K (rows of B)
            a0 = *reinterpret_cast<const float4*>(An + (size_t)aRow      * lda + aCol);
            a1 = *reinterpret_cast<const float4*>(An + (size_t)(aRow+64) * lda + aCol);
            b0 = *reinterpret_cast<const float4*>(Bn + (size_t)bRow      * ldb + bCol);
            b1 = *reinterpret_cast<const float4*>(Bn + (size_t)(bRow+8)  * ldb + bCol);
        }

        #pragma unroll
        for (int kk = 0; kk < 16; kk++) {
            float a[8], b[8];
            *reinterpret_cast<float4*>(a)   = *reinterpret_cast<const float4*>(&As[cur][kk][ty]);
            *reinterpret_cast<float4*>(a+4) = *reinterpret_cast<const float4*>(&As[cur][kk][ty+4]);
            *reinterpret_cast<float4*>(b)   = *reinterpret_cast<const float4*>(&Bs[cur][kk][tx]);
            *reinterpret_cast<float4*>(b+4) = *reinterpret_cast<const float4*>(&Bs[cur][kk][tx+4]);
            #pragma unroll
            for (int i = 0; i < 8; i++)
                #pragma unroll
                for (int j = 0; j < 8; j++)
                    acc[i][j] = fmaf(a[i], b[j], acc[i][j]);
        }

        if (t + 1 < T) {
            const int nxt = cur ^ 1;
            As[nxt][aCol+0][aRow]    = a0.x; As[nxt][aCol+1][aRow]    = a0.y;
            As[nxt][aCol+2][aRow]    = a0.z; As[nxt][aCol+3][aRow]    = a0.w;
            As[nxt][aCol+0][aRow+64] = a1.x; As[nxt][aCol+1][aRow+64] = a1.y;
            As[nxt][aCol+2][aRow+64] = a1.z; As[nxt][aCol+3][aRow+64] = a1.w;
            *reinterpret_cast<float4*>(&Bs[nxt][bRow  ][bCol]) = b0;
            *reinterpret_cast<float4*>(&Bs[nxt][bRow+8][bCol]) = b1;
            __syncthreads();
        }
    }
}

// ---------------------------------------------------------------------------
// Encoder: f = relu(X[1024,2048] @ W_enc[2048,32768] + b_enc)  -> g_f
// grid (8, 256), block 256
// ---------------------------------------------------------------------------
__global__ __launch_bounds__(256, 2)
void enc_kernel(const float* __restrict__ x,
                const float* __restrict__ W,
                const float* __restrict__ bias)
{
    __shared__ float As[2][16][128];
    __shared__ float Bs[2][16][128];
    float acc[8][8];
    #pragma unroll
    for (int i = 0; i < 8; i++)
        #pragma unroll
        for (int j = 0; j < 8; j++) acc[i][j] = 0.0f;

    const float* A  = x + (size_t)blockIdx.x * 128 * K1;
    const float* Bp = W + (size_t)blockIdx.y * 128;
    gemm_tile(A, K1, Bp, F_, K1, acc, As, Bs);

    const int tid = threadIdx.x;
    const int tx  = (tid & 15) << 3;
    const int ty  = (tid >> 4) << 3;
    const int row0 = blockIdx.x * 128 + ty;
    const int col0 = blockIdx.y * 128 + tx;

    float bi[8];
    *reinterpret_cast<float4*>(bi)   = *reinterpret_cast<const float4*>(&bias[col0]);
    *reinterpret_cast<float4*>(bi+4) = *reinterpret_cast<const float4*>(&bias[col0+4]);

    #pragma unroll
    for (int i = 0; i < 8; i++) {
        float4 v0, v1;
        v0.x = fmaxf(acc[i][0] + bi[0], 0.0f);
        v0.y = fmaxf(acc[i][1] + bi[1], 0.0f);
        v0.z = fmaxf(acc[i][2] + bi[2], 0.0f);
        v0.w = fmaxf(acc[i][3] + bi[3], 0.0f);
        v1.x = fmaxf(acc[i][4] + bi[4], 0.0f);
        v1.y = fmaxf(acc[i][5] + bi[5], 0.0f);
        v1.z = fmaxf(acc[i][6] + bi[6], 0.0f);
        v1.w = fmaxf(acc[i][7] + bi[7], 0.0f);
        float* dst = g_f + (size_t)(row0 + i) * F_ + col0;
        *reinterpret_cast<float4*>(dst)     = v0;
        *reinterpret_cast<float4*>(dst + 4) = v1;
    }
}

// ---------------------------------------------------------------------------
// Decoder split-K partials: part[kz] = f[:, kz*8192:(kz+1)*8192] @ Wd_l slice
// grid (8, 16, SPLITK), block 256.  Column j = l*D + d; a 128-wide tile stays
// within one l, so B is a plain row-major [F,1024] slab per l.
// ---------------------------------------------------------------------------
__global__ __launch_bounds__(256, 2)
void dec_kernel(const float* __restrict__ Wd)
{
    __shared__ float As[2][16][128];
    __shared__ float Bs[2][16][128];
    float acc[8][8];
    #pragma unroll
    for (int i = 0; i < 8; i++)
        #pragma unroll
        for (int j = 0; j < 8; j++) acc[i][j] = 0.0f;

    const int n0 = blockIdx.y * 128;
    const int l  = n0 / D_;
    const int d0 = n0 % D_;
    const int kz = blockIdx.z;

    const float* A  = g_f + (size_t)blockIdx.x * 128 * F_ + (size_t)kz * KSPL;
    const float* Bp = Wd + (size_t)l * F_ * D_ + (size_t)kz * KSPL * D_ + d0;
    gemm_tile(A, F_, Bp, D_, KSPL, acc, As, Bs);

    const int tid = threadIdx.x;
    const int tx  = (tid & 15) << 3;
    const int ty  = (tid >> 4) << 3;
    const int row0 = blockIdx.x * 128 + ty;
    const int col0 = n0 + tx;

    float* C = g_part + (size_t)kz * B_ * N2;
    #pragma unroll
    for (int i = 0; i < 8; i++) {
        float4 v0, v1;
        v0.x = acc[i][0]; v0.y = acc[i][1]; v0.z = acc[i][2]; v0.w = acc[i][3];
        v1.x = acc[i][4]; v1.y = acc[i][5]; v1.z = acc[i][6]; v1.w = acc[i][7];
        float* dst = C + (size_t)(row0 + i) * N2 + col0;
        *reinterpret_cast<float4*>(dst)     = v0;
        *reinterpret_cast<float4*>(dst + 4) = v1;
    }
}

// ---------------------------------------------------------------------------
// Reduce split-K partials + b_dec -> output [B, L*D]
// ---------------------------------------------------------------------------
__global__ void reduce_kernel(float* __restrict__ out,
                              const float* __restrict__ b_dec)
{
    const size_t i  = (size_t)blockIdx.x * blockDim.x + threadIdx.x; // float4 idx
    const size_t n4 = (size_t)B_ * N2 / 4;                           // 524288
    if (i >= n4) return;
    const float4* p = reinterpret_cast<const float4*>(g_part);
    float4 v0 = p[i];
    float4 v1 = p[i + n4];
    float4 v2 = p[i + 2*n4];
    float4 v3 = p[i + 3*n4];
    const int col = (int)((i * 4) & (N2 - 1));
    float4 bb = *reinterpret_cast<const float4*>(&b_dec[col]);
    float4 r;
    r.x = v0.x + v1.x + v2.x + v3.x + bb.x;
    r.y = v0.y + v1.y + v2.y + v3.y + bb.y;
    r.z = v0.z + v1.z + v2.z + v3.z + bb.z;
    r.w = v0.w + v1.w + v2.w + v3.w + bb.w;
    reinterpret_cast<float4*>(out)[i] = r;
}

// ---------------------------------------------------------------------------
extern "C" void kernel_launch(void* const* d_in, const int* in_sizes, int n_in,
                              void* d_out, int out_size)
{
    const float* x     = (const float*)d_in[0];
    const float* W_enc = (const float*)d_in[1];
    const float* b_enc = (const float*)d_in[2];
    const float* W_dec = (const float*)d_in[3];
    const float* b_dec = (const float*)d_in[4];
    float* out = (float*)d_out;

    dim3 ge(8, 256);
    enc_kernel<<<ge, 256>>>(x, W_enc, b_enc);

    dim3 gd(8, 16, SPLITK);
    dec_kernel<<<gd, 256>>>(W_dec);

    reduce_kernel<<<2048, 256>>>(out, b_dec);
}